// round 2
// baseline (speedup 1.0000x reference)
#include <cuda_runtime.h>

#define BATCH 4
#define SEQ   1024
#define DIMC  1024
#define HEADS 16
#define HD    64
#define BH    (BATCH*HEADS)

// ---------------- scratch (static device globals; no allocs) ----------------
__device__ float g_qkv [(size_t)BATCH*SEQ*3*DIMC];   // 50 MB
__device__ float g_q   [(size_t)BH*SEQ*HD];          // 16.8 MB
__device__ float g_k   [(size_t)BH*SEQ*HD];
__device__ float g_v   [(size_t)BH*SEQ*HD];
__device__ float g_R   [(size_t)BH*SEQ*SEQ];         // 268 MB
__device__ float g_S   [(size_t)BH*SEQ*SEQ];         // 268 MB (scores, then probs in place)
__device__ float g_attn[(size_t)BATCH*SEQ*DIMC];     // 16.8 MB

// ---------------- generic strided batched SGEMM: C[m,n] = sum_k A[m,k]*B[n,k] ----------------
// A addr: (m*lam + k*lak), B addr: (n*lbn + k*lbk), C addr: (m*lcm + n*lcn)
// batch z: b = z/H, h = z%H; per-array offsets b*s?b + h*s?h.
template<int BM, int BN, int BK, int TM, int TN>
__global__ __launch_bounds__((BM/TM)*(BN/TN))
void gemm_kernel(const float* __restrict__ A, const float* __restrict__ B,
                 float* __restrict__ C, const float* __restrict__ bias,
                 int K, int H,
                 long lam, long lak, long lbn, long lbk, long lcm, long lcn,
                 long sAb, long sAh, long sBb, long sBh, long sCb, long sCh,
                 int causal)
{
    constexpr int THREADS = (BM/TM)*(BN/TN);
    const int m0 = blockIdx.x * BM;
    const int n0 = blockIdx.y * BN;
    if (causal && n0 > m0 + BM - 1) return;   // fully-masked key block

    const int z  = blockIdx.z;
    const int zb = z / H;
    const int zh = z - zb * H;
    A += (long)zb * sAb + (long)zh * sAh;
    B += (long)zb * sBb + (long)zh * sBh;
    C += (long)zb * sCb + (long)zh * sCh;

    __shared__ float As[BK][BM + 4];
    __shared__ float Bs[BK][BN + 4];

    const int tid = threadIdx.x;
    const int tx  = tid % (BN / TN);
    const int ty  = tid / (BN / TN);

    float acc[TM][TN];
#pragma unroll
    for (int i = 0; i < TM; i++)
#pragma unroll
        for (int j = 0; j < TN; j++) acc[i][j] = 0.0f;

    for (int k0 = 0; k0 < K; k0 += BK) {
        // load A tile (all call sites have lak==1; mapping is k-fast for coalescing)
#pragma unroll
        for (int i = 0; i < (BM * BK) / THREADS; i++) {
            int lin = tid + i * THREADS;
            int mm = lin / BK, kk = lin - mm * BK;
            As[kk][mm] = A[(long)(m0 + mm) * lam + (long)(k0 + kk) * lak];
        }
        if (lbk == 1) {
#pragma unroll
            for (int i = 0; i < (BN * BK) / THREADS; i++) {
                int lin = tid + i * THREADS;
                int nn = lin / BK, kk = lin - nn * BK;
                Bs[kk][nn] = B[(long)(n0 + nn) * lbn + (long)(k0 + kk)];
            }
        } else {  // B contiguous along n (P@V case): n-fast mapping for coalescing
#pragma unroll
            for (int i = 0; i < (BN * BK) / THREADS; i++) {
                int lin = tid + i * THREADS;
                int kk = lin / BN, nn = lin - kk * BN;
                Bs[kk][nn] = B[(long)(n0 + nn) * lbn + (long)(k0 + kk) * lbk];
            }
        }
        __syncthreads();

#pragma unroll
        for (int kk = 0; kk < BK; kk++) {
            float a[TM], b[TN];
#pragma unroll
            for (int i = 0; i < TM; i += 4)
                *(float4*)&a[i] = *(const float4*)&As[kk][ty * TM + i];
#pragma unroll
            for (int j = 0; j < TN; j += 4)
                *(float4*)&b[j] = *(const float4*)&Bs[kk][tx * TN + j];
#pragma unroll
            for (int i = 0; i < TM; i++)
#pragma unroll
                for (int j = 0; j < TN; j++)
                    acc[i][j] += a[i] * b[j];
        }
        __syncthreads();
    }

#pragma unroll
    for (int i = 0; i < TM; i++) {
        long crow = (long)(m0 + ty * TM + i) * lcm;
#pragma unroll
        for (int j = 0; j < TN; j++) {
            int nc = n0 + tx * TN + j;
            float vv = acc[i][j];
            if (bias) vv += bias[nc];
            C[crow + (long)nc * lcn] = vv;
        }
    }
}

// ---------------- pack qkv[b,n,3*D] -> q/k/v[bh, n, hd] ----------------
__global__ void pack_kernel(const float* __restrict__ qkv,
                            float* __restrict__ q, float* __restrict__ k, float* __restrict__ v)
{
    long idx = (long)blockIdx.x * blockDim.x + threadIdx.x;
    const long total = (long)BATCH * SEQ * 3 * DIMC;
    if (idx >= total) return;
    int  f  = (int)(idx % (3 * DIMC));
    long bn = idx / (3 * DIMC);
    int which = f / DIMC;
    int hf = f - which * DIMC;
    int h = hf >> 6;          // /64
    int d = hf & 63;
    int b = (int)(bn >> 10);  // /1024
    int n = (int)(bn & 1023);
    long dst = (((long)(b * HEADS + h) * SEQ) + n) * HD + d;
    float val = qkv[idx];
    float* p = (which == 0) ? q : (which == 1) ? k : v;
    p[dst] = val;
}

// ---------------- fused skew-gather + scale + causal mask + softmax (in place on S) ------------
// rel_skewed[n,m] = R[n, N-1-n+m]  for m <= n   (derived from pad/reshape/slice skew)
__global__ void softmax_kernel(float* __restrict__ S, const float* __restrict__ R)
{
    const int Nn = SEQ;
    int row = blockIdx.x;           // row = z*SEQ + n
    int n = row & (Nn - 1);
    int z = row >> 10;
    float* srow = S + (long)row * Nn;
    const float* rrow = R + (long)z * Nn * Nn + (long)n * Nn;
    int t = threadIdx.x;

    float vals[4];
    float mx = -1e30f;
#pragma unroll
    for (int i = 0; i < 4; i++) {
        int m = t + i * 256;
        float v = -1e30f;
        if (m <= n) v = (srow[m] + rrow[Nn - 1 - n + m]) * 0.125f;  // 64^-0.5
        vals[i] = v;
        mx = fmaxf(mx, v);
    }
    __shared__ float red[256];
    red[t] = mx; __syncthreads();
    for (int s = 128; s; s >>= 1) { if (t < s) red[t] = fmaxf(red[t], red[t + s]); __syncthreads(); }
    mx = red[0];
    __syncthreads();

    float sum = 0.0f;
#pragma unroll
    for (int i = 0; i < 4; i++) { vals[i] = __expf(vals[i] - mx); sum += vals[i]; }
    red[t] = sum; __syncthreads();
    for (int s = 128; s; s >>= 1) { if (t < s) red[t] += red[t + s]; __syncthreads(); }
    float inv = 1.0f / red[0];
#pragma unroll
    for (int i = 0; i < 4; i++) srow[t + i * 256] = vals[i] * inv;
}

// ---------------- launch ----------------
extern "C" void kernel_launch(void* const* d_in, const int* in_sizes, int n_in,
                              void* d_out, int out_size)
{
    const float* x     = (const float*)d_in[0];   // [4,1024,1024]
    const float* Wqkv  = (const float*)d_in[1];   // [3072,1024]
    const float* Wproj = (const float*)d_in[2];   // [1024,1024]
    const float* bproj = (const float*)d_in[3];   // [1024]
    const float* Er    = (const float*)d_in[4];   // [1024,64]
    float* out = (float*)d_out;

    float *qkv, *q, *k, *v, *R, *S, *attn;
    cudaGetSymbolAddress((void**)&qkv,  g_qkv);
    cudaGetSymbolAddress((void**)&q,    g_q);
    cudaGetSymbolAddress((void**)&k,    g_k);
    cudaGetSymbolAddress((void**)&v,    g_v);
    cudaGetSymbolAddress((void**)&R,    g_R);
    cudaGetSymbolAddress((void**)&S,    g_S);
    cudaGetSymbolAddress((void**)&attn, g_attn);

    // 1) qkv = x @ Wqkv^T   (M=4096, N=3072, K=1024)
    gemm_kernel<128,128,8,8,8><<<dim3(32,24,1), 256>>>(
        x, Wqkv, qkv, nullptr, 1024, 1,
        /*lam,lak*/1024,1, /*lbn,lbk*/1024,1, /*lcm,lcn*/3072,1,
        0,0, 0,0, 0,0, 0);

    // 2) pack q/k/v
    pack_kernel<<<(BATCH*SEQ*3*DIMC)/256, 256>>>(qkv, q, k, v);

    // 3) R[z] = q[z] @ Er^T   (z=bh, M=1024, N=1024, K=64)
    gemm_kernel<128,128,8,8,8><<<dim3(8,8,BH), 256>>>(
        q, Er, R, nullptr, 64, 1,
        64,1, 64,1, 1024,1,
        (long)SEQ*HD,0, 0,0, (long)SEQ*SEQ,0, 0);

    // 4) S[z] = q[z] @ k[z]^T   (causal block skip)
    gemm_kernel<128,128,8,8,8><<<dim3(8,8,BH), 256>>>(
        q, k, S, nullptr, 64, 1,
        64,1, 64,1, 1024,1,
        (long)SEQ*HD,0, (long)SEQ*HD,0, (long)SEQ*SEQ,0, 1);

    // 5) fused skew + scale + mask + softmax (in place)
    softmax_kernel<<<BH*SEQ, 256>>>(S, R);

    // 6) attn[b,n,h*64+d] = P[z] @ v[z]   (M=1024, N=64, K=1024)
    gemm_kernel<128,64,8,8,4><<<dim3(8,1,BH), 256>>>(
        S, v, attn, nullptr, 1024, HEADS,
        /*lam,lak*/1024,1, /*lbn,lbk*/1,64, /*lcm,lcn*/1024,1,
        (long)HEADS*SEQ*SEQ,(long)SEQ*SEQ,
        (long)HEADS*SEQ*HD,(long)SEQ*HD,
        (long)SEQ*DIMC,(long)HD, 0);

    // 7) out = attn @ Wproj^T + b   (M=4096, N=1024, K=1024)
    gemm_kernel<128,128,8,8,8><<<dim3(32,8,1), 256>>>(
        attn, Wproj, out, bproj, 1024, 1,
        1024,1, 1024,1, 1024,1,
        0,0, 0,0, 0,0, 0);
}

// round 3
// speedup vs baseline: 1.8864x; 1.8864x over previous
#include <cuda_runtime.h>

#define BATCH 4
#define SEQ   1024
#define DIMC  1024
#define HEADS 16
#define HD    64
#define BH    (BATCH*HEADS)

typedef unsigned long long ull;

// ---------------- packed f32x2 helpers (sm_103a FFMA2 path) ----------------
__device__ __forceinline__ ull fma2(ull a, ull b, ull c) {
    ull d; asm("fma.rn.f32x2 %0, %1, %2, %3;" : "=l"(d) : "l"(a), "l"(b), "l"(c)); return d;
}
__device__ __forceinline__ ull mul2(ull a, ull b) {
    ull d; asm("mul.rn.f32x2 %0, %1, %2;" : "=l"(d) : "l"(a), "l"(b)); return d;
}
__device__ __forceinline__ ull pack2(float lo, float hi) {
    ull d; asm("mov.b64 %0, {%1, %2};" : "=l"(d) : "f"(lo), "f"(hi)); return d;
}
__device__ __forceinline__ ull dup2(float v) { return pack2(v, v); }
__device__ __forceinline__ float2 unpack2(ull a) {
    float2 r; asm("mov.b64 {%0, %1}, %2;" : "=f"(r.x), "=f"(r.y) : "l"(a)); return r;
}

// ---------------- scratch ----------------
__device__ float g_qkv [(size_t)BATCH*SEQ*3*DIMC];   // 50 MB
__device__ float g_attn[(size_t)BATCH*SEQ*DIMC];     // 16.8 MB

// ---------------- SGEMM with f32x2 micro-kernel: C[m,n] = sum_k A[m,k]*B[n,k] ----------------
// A row-major [M,lam] k-contig, B row-major [N,lbn] k-contig, C row-major [M,lcm].
template<int BM, int BN, int BK, int TM, int TN>
__global__ __launch_bounds__((BM/TM)*(BN/TN))
void gemm_kernel(const float* __restrict__ A, const float* __restrict__ B,
                 float* __restrict__ C, const float* __restrict__ bias,
                 int K, int lam, int lbn, int lcm)
{
    constexpr int THREADS = (BM/TM)*(BN/TN);
    const int m0 = blockIdx.x * BM;
    const int n0 = blockIdx.y * BN;

    __shared__ __align__(16) float As[BK][BM + 4];
    __shared__ __align__(16) float Bs[BK][BN + 4];

    const int tid = threadIdx.x;
    const int tx  = tid % (BN / TN);
    const int ty  = tid / (BN / TN);

    ull acc2[TM][TN/2];
#pragma unroll
    for (int i = 0; i < TM; i++)
#pragma unroll
        for (int jp = 0; jp < TN/2; jp++) acc2[i][jp] = 0ull;

    for (int k0 = 0; k0 < K; k0 += BK) {
#pragma unroll
        for (int i = 0; i < (BM * BK) / THREADS; i++) {
            int lin = tid + i * THREADS;
            int mm = lin / BK, kk = lin - mm * BK;
            As[kk][mm] = A[(size_t)(m0 + mm) * lam + (k0 + kk)];
        }
#pragma unroll
        for (int i = 0; i < (BN * BK) / THREADS; i++) {
            int lin = tid + i * THREADS;
            int nn = lin / BK, kk = lin - nn * BK;
            Bs[kk][nn] = B[(size_t)(n0 + nn) * lbn + (k0 + kk)];
        }
        __syncthreads();

#pragma unroll
        for (int kk = 0; kk < BK; kk++) {
            float a[TM];
#pragma unroll
            for (int i = 0; i < TM; i += 4)
                *(float4*)&a[i] = *(const float4*)&As[kk][ty * TM + i];
            ull b2[TN/2];
#pragma unroll
            for (int jp = 0; jp < TN/2; jp++)
                b2[jp] = *(const ull*)&Bs[kk][tx * TN + 2*jp];
#pragma unroll
            for (int i = 0; i < TM; i++) {
                ull a2 = dup2(a[i]);
#pragma unroll
                for (int jp = 0; jp < TN/2; jp++)
                    acc2[i][jp] = fma2(a2, b2[jp], acc2[i][jp]);
            }
        }
        __syncthreads();
    }

#pragma unroll
    for (int i = 0; i < TM; i++) {
        float* crow = C + (size_t)(m0 + ty * TM + i) * lcm;
#pragma unroll
        for (int jp = 0; jp < TN/2; jp++) {
            int nc = n0 + tx * TN + 2*jp;
            float2 v = unpack2(acc2[i][jp]);
            if (bias) { v.x += bias[nc]; v.y += bias[nc + 1]; }
            crow[nc]     = v.x;
            crow[nc + 1] = v.y;
        }
    }
}

// ---------------- fused flash attention with relative-position skew ----------------
// Per block: one (z = b*16+h, 64-row q tile). Online softmax over 64-col kv tiles.
// rel[n,m] = q_n . Er[N-1-n+m]  (m <= n); per kv-tile Er window j0 = N-64-i0+kt0,
// local index = (4tx+j) - (4ty+i) + 63  in [0,126].
#define QT_S 68
#define KT_S 68
#define VS_S 68
#define SS_S 68
#define ER_S 132
#define RED_S 17
#define FLASH_SMEM_FLOATS (64*QT_S + 64*KT_S + 64*VS_S + 64*ER_S + 64*SS_S + 64*RED_S + 3*64)
#define FLASH_SMEM_BYTES  (FLASH_SMEM_FLOATS * 4)

__global__ __launch_bounds__(256, 2)
void flash_kernel(const float* __restrict__ qkv, const float* __restrict__ Er,
                  float* __restrict__ attn)
{
    extern __shared__ __align__(16) float sm[];
    float* Qt    = sm;
    float* Kt    = Qt  + 64*QT_S;
    float* Vs    = Kt  + 64*KT_S;
    float* ErT   = Vs  + 64*VS_S;
    float* Ss    = ErT + 64*ER_S;
    float* red   = Ss  + 64*SS_S;
    float* rowM  = red + 64*RED_S;
    float* rowL  = rowM + 64;
    float* rowSc = rowL + 64;

    const int z  = blockIdx.y;
    const int b  = z >> 4, h = z & 15;
    const int i0 = (int)(gridDim.x - 1 - blockIdx.x) * 64;  // heavy tiles first
    const int tid = threadIdx.x;
    const int tx = tid & 15, ty = tid >> 4;
    const int RS = 3 * DIMC;

    const float* qb = qkv + (size_t)b * SEQ * RS + h * HD;  // q[n][d] = qb[n*RS+d]
    const float* kb = qb + DIMC;
    const float* vb = qb + 2 * DIMC;

    // load Q tile transposed: Qt[d][n]  (conflict-free scatter: lanes vary n)
#pragma unroll
    for (int s = 0; s < 4; s++) {
        int vv = tid + 256 * s;
        int ln = vv & 63, dq = (vv >> 6) << 2;
        float4 t = *(const float4*)&qb[(size_t)(i0 + ln) * RS + dq];
        Qt[(dq+0)*QT_S + ln] = t.x; Qt[(dq+1)*QT_S + ln] = t.y;
        Qt[(dq+2)*QT_S + ln] = t.z; Qt[(dq+3)*QT_S + ln] = t.w;
    }
    if (tid < 64) { rowM[tid] = -1e30f; rowL[tid] = 0.0f; }

    ull o2[4][2];
#pragma unroll
    for (int i = 0; i < 4; i++) { o2[i][0] = 0ull; o2[i][1] = 0ull; }

    const int ntiles = i0 / 64 + 1;
    for (int kt = 0; kt < ntiles; kt++) {
        const int kt0 = kt * 64;
        __syncthreads();  // protect Kt/Vs/ErT/red reuse

        // K transposed + V direct
#pragma unroll
        for (int s = 0; s < 4; s++) {
            int vv = tid + 256 * s;
            int ln = vv & 63, dq = (vv >> 6) << 2;
            float4 t = *(const float4*)&kb[(size_t)(kt0 + ln) * RS + dq];
            Kt[(dq+0)*KT_S + ln] = t.x; Kt[(dq+1)*KT_S + ln] = t.y;
            Kt[(dq+2)*KT_S + ln] = t.z; Kt[(dq+3)*KT_S + ln] = t.w;
            int lm = vv >> 4, dv = (vv & 15) << 2;
            float4 u = *(const float4*)&vb[(size_t)(kt0 + lm) * RS + dv];
            *(float4*)&Vs[lm * VS_S + dv] = u;
        }
        // Er window transposed: rows j0..j0+127 (clamp >= SEQ to zero)
        const int j0 = SEQ - 64 - i0 + kt0;
#pragma unroll
        for (int s = 0; s < 8; s++) {
            int vv = tid + 256 * s;
            int jl = vv & 127, dq = (vv >> 7) << 2;
            int j = j0 + jl;
            float4 t = make_float4(0.f, 0.f, 0.f, 0.f);
            if (j < SEQ) t = *(const float4*)&Er[(size_t)j * HD + dq];
            ErT[(dq+0)*ER_S + jl] = t.x; ErT[(dq+1)*ER_S + jl] = t.y;
            ErT[(dq+2)*ER_S + jl] = t.z; ErT[(dq+3)*ER_S + jl] = t.w;
        }
        __syncthreads();

        // S = Q.K^T (packed f32x2) + rel (scalar), over d=0..63
        ull  c2[4][2];
        float rel[4][4];
#pragma unroll
        for (int i = 0; i < 4; i++) {
            c2[i][0] = 0ull; c2[i][1] = 0ull;
#pragma unroll
            for (int j = 0; j < 4; j++) rel[i][j] = 0.0f;
        }
        const int ebase = 4*tx - 4*ty + 60;   // multiple of 4, in [0,120]
#pragma unroll 4
        for (int kk = 0; kk < 64; kk++) {
            float a[4];
            *(float4*)&a[0] = *(const float4*)&Qt[kk * QT_S + 4*ty];
            ull b0 = *(const ull*)&Kt[kk * KT_S + 4*tx];
            ull b1 = *(const ull*)&Kt[kk * KT_S + 4*tx + 2];
            float e[8];
            *(float4*)&e[0] = *(const float4*)&ErT[kk * ER_S + ebase];
            *(float4*)&e[4] = *(const float4*)&ErT[kk * ER_S + ebase + 4];
#pragma unroll
            for (int i = 0; i < 4; i++) {
                ull a2 = dup2(a[i]);
                c2[i][0] = fma2(a2, b0, c2[i][0]);
                c2[i][1] = fma2(a2, b1, c2[i][1]);
#pragma unroll
                for (int j = 0; j < 4; j++)
                    rel[i][j] += a[i] * e[j - i + 3];
            }
        }

        // combine + scale + causal mask + tile row max
        float sv[4][4];
#pragma unroll
        for (int i = 0; i < 4; i++) {
            const int n = i0 + 4*ty + i;
            float2 p0 = unpack2(c2[i][0]), p1 = unpack2(c2[i][1]);
            sv[i][0] = p0.x + rel[i][0]; sv[i][1] = p0.y + rel[i][1];
            sv[i][2] = p1.x + rel[i][2]; sv[i][3] = p1.y + rel[i][3];
            float mx = -1e30f;
#pragma unroll
            for (int j = 0; j < 4; j++) {
                int m = kt0 + 4*tx + j;
                sv[i][j] = (m <= n) ? sv[i][j] * 0.125f : -1e30f;
                mx = fmaxf(mx, sv[i][j]);
            }
            red[(4*ty + i) * RED_S + tx] = mx;
        }
        __syncthreads();
        if (tid < 64) {
            float tm = -1e30f;
#pragma unroll
            for (int t = 0; t < 16; t++) tm = fmaxf(tm, red[tid * RED_S + t]);
            float om = rowM[tid];
            float nm = fmaxf(om, tm);
            rowSc[tid] = __expf(om - nm);
            rowM[tid]  = nm;
        }
        __syncthreads();

        // p = exp(s - m), write P tile + row partial sums
#pragma unroll
        for (int i = 0; i < 4; i++) {
            const int r = 4*ty + i;
            const float mrow = rowM[r];
            float ps = 0.0f;
#pragma unroll
            for (int j = 0; j < 4; j++) {
                float p = __expf(sv[i][j] - mrow);
                ps += p;
                Ss[r * SS_S + 4*tx + j] = p;
            }
            red[r * RED_S + tx] = ps;
        }
        __syncthreads();
        if (tid < 64) {
            float s = 0.0f;
#pragma unroll
            for (int t = 0; t < 16; t++) s += red[tid * RED_S + t];
            rowL[tid] = rowL[tid] * rowSc[tid] + s;
        }

        // rescale O, then O += P @ V (packed along d)
#pragma unroll
        for (int i = 0; i < 4; i++) {
            ull sc = dup2(rowSc[4*ty + i]);
            o2[i][0] = mul2(o2[i][0], sc);
            o2[i][1] = mul2(o2[i][1], sc);
        }
#pragma unroll 4
        for (int m = 0; m < 64; m++) {
            ull b0 = *(const ull*)&Vs[m * VS_S + 4*tx];
            ull b1 = *(const ull*)&Vs[m * VS_S + 4*tx + 2];
#pragma unroll
            for (int i = 0; i < 4; i++) {
                ull a2 = dup2(Ss[(4*ty + i) * SS_S + m]);
                o2[i][0] = fma2(a2, b0, o2[i][0]);
                o2[i][1] = fma2(a2, b1, o2[i][1]);
            }
        }
    }
    __syncthreads();  // rowL final

    // write O / rowL to attn[b][n][h*64+d]
#pragma unroll
    for (int i = 0; i < 4; i++) {
        const int n = i0 + 4*ty + i;
        const float inv = 1.0f / rowL[4*ty + i];
        float2 p0 = unpack2(o2[i][0]), p1 = unpack2(o2[i][1]);
        float* dst = attn + ((size_t)b * SEQ + n) * DIMC + h * HD + 4*tx;
        dst[0] = p0.x * inv; dst[1] = p0.y * inv;
        dst[2] = p1.x * inv; dst[3] = p1.y * inv;
    }
}

// ---------------- launch ----------------
extern "C" void kernel_launch(void* const* d_in, const int* in_sizes, int n_in,
                              void* d_out, int out_size)
{
    const float* x     = (const float*)d_in[0];   // [4,1024,1024]
    const float* Wqkv  = (const float*)d_in[1];   // [3072,1024]
    const float* Wproj = (const float*)d_in[2];   // [1024,1024]
    const float* bproj = (const float*)d_in[3];   // [1024]
    const float* Er    = (const float*)d_in[4];   // [1024,64]
    float* out = (float*)d_out;

    float *qkv, *attn;
    cudaGetSymbolAddress((void**)&qkv,  g_qkv);
    cudaGetSymbolAddress((void**)&attn, g_attn);

    // 1) qkv = x @ Wqkv^T   (M=4096, N=3072, K=1024)
    gemm_kernel<128,128,16,8,8><<<dim3(32, 24), 256>>>(
        x, Wqkv, qkv, nullptr, 1024, 1024, 1024, 3072);

    // 2) fused attention (content + rel-skew + causal softmax + P@V)
    cudaFuncSetAttribute(flash_kernel, cudaFuncAttributeMaxDynamicSharedMemorySize,
                         FLASH_SMEM_BYTES);
    flash_kernel<<<dim3(16, 64), 256, FLASH_SMEM_BYTES>>>(qkv, Er, attn);

    // 3) out = attn @ Wproj^T + b   (M=4096, N=1024, K=1024)
    gemm_kernel<128,128,16,8,8><<<dim3(32, 8), 256>>>(
        attn, Wproj, out, bproj, 1024, 1024, 1024, 1024);
}

// round 6
// speedup vs baseline: 3.4004x; 1.8025x over previous
#include <cuda_runtime.h>
#include <cstdint>

#define BATCH 4
#define SEQ   1024
#define DIMC  1024
#define HEADS 16
#define HD    64
#define BH    (BATCH*HEADS)

typedef unsigned long long ull;

// ---------------- packed f32x2 helpers (flash kernel) ----------------
__device__ __forceinline__ ull fma2(ull a, ull b, ull c) {
    ull d; asm("fma.rn.f32x2 %0, %1, %2, %3;" : "=l"(d) : "l"(a), "l"(b), "l"(c)); return d;
}
__device__ __forceinline__ ull mul2(ull a, ull b) {
    ull d; asm("mul.rn.f32x2 %0, %1, %2;" : "=l"(d) : "l"(a), "l"(b)); return d;
}
__device__ __forceinline__ ull pack2(float lo, float hi) {
    ull d; asm("mov.b64 %0, {%1, %2};" : "=l"(d) : "f"(lo), "f"(hi)); return d;
}
__device__ __forceinline__ ull dup2(float v) { return pack2(v, v); }
__device__ __forceinline__ float2 unpack2(ull a) {
    float2 r; asm("mov.b64 {%0, %1}, %2;" : "=f"(r.x), "=f"(r.y) : "l"(a)); return r;
}

// ---------------- cp.async helpers ----------------
__device__ __forceinline__ uint32_t smem_u32(const void* p) {
    uint32_t a;
    asm("{ .reg .u64 t; cvta.to.shared.u64 t, %1; cvt.u32.u64 %0, t; }" : "=r"(a) : "l"(p));
    return a;
}
__device__ __forceinline__ void cpa16(uint32_t dst, const void* src) {
    asm volatile("cp.async.cg.shared.global [%0], [%1], 16;" :: "r"(dst), "l"(src));
}
#define CP_COMMIT() asm volatile("cp.async.commit_group;" ::: "memory")
#define CP_WAIT(n)  asm volatile("cp.async.wait_group %0;" :: "n"(n) : "memory")

// ---------------- scratch ----------------
__device__ __align__(16) float g_qkv  [(size_t)BATCH*SEQ*3*DIMC];   // 50 MB
__device__ __align__(16) float g_attn [(size_t)BATCH*SEQ*DIMC];     // 16.8 MB
__device__ __align__(16) float g_xt   [(size_t)BATCH*SEQ*DIMC];     // tf32-rounded copies
__device__ __align__(16) float g_wqkvt[(size_t)3*DIMC*DIMC];
__device__ __align__(16) float g_attnt[(size_t)BATCH*SEQ*DIMC];
__device__ __align__(16) float g_wprojt[(size_t)DIMC*DIMC];

// ---------------- round fp32 -> tf32 (rna) elementwise ----------------
__global__ void conv_tf32(const float* __restrict__ in, float* __restrict__ out, int total)
{
    int i = (blockIdx.x * blockDim.x + threadIdx.x) * 4;
    if (i >= total) return;
    float4 v = *(const float4*)(in + i);
    uint4 o;
    asm("cvt.rna.tf32.f32 %0, %1;" : "=r"(o.x) : "f"(v.x));
    asm("cvt.rna.tf32.f32 %0, %1;" : "=r"(o.y) : "f"(v.y));
    asm("cvt.rna.tf32.f32 %0, %1;" : "=r"(o.z) : "f"(v.z));
    asm("cvt.rna.tf32.f32 %0, %1;" : "=r"(o.w) : "f"(v.w));
    *(uint4*)(out + i) = o;
}

// ---------------- tf32 mma.sync GEMM: C[m,n] = sum_k A[m,k]*B[n,k] ----------------
// A [M,K], B [N,K] fp32(tf32-rounded) row-major k-contig; C fp32 [M,ldc].
// 128x128 CTA tile, 8 warps (64x32 warp tiles), K-chunk 32, cp.async double buffer.
#define TILE_W 36
#define TILE_WORDS (128*TILE_W)
#define GSMEM_BYTES (2*2*TILE_WORDS*4)   // 73728

__global__ __launch_bounds__(256, 2)
void tf32_gemm(const float* __restrict__ A, const float* __restrict__ B,
               float* __restrict__ C, const float* __restrict__ bias, int K, int ldc)
{
    extern __shared__ __align__(16) float sm[];
    const int tid = threadIdx.x, w = tid >> 5, t = tid & 31;
    const int m0 = blockIdx.x * 128, n0 = blockIdx.y * 128;
    const int wm = (w >> 2) * 64, wn = (w & 3) * 32;
    const int g = t >> 2, th = t & 3;

    float acc[4][4][4];
#pragma unroll
    for (int mt = 0; mt < 4; mt++)
#pragma unroll
        for (int nt = 0; nt < 4; nt++)
#pragma unroll
            for (int r = 0; r < 4; r++) acc[mt][nt][r] = 0.0f;

    const int lr = tid >> 3;            // 0..31
    const int lc = (tid & 7) << 2;      // 0,4,...,28

#define PREFETCH(kt, s) do {                                                   \
        float* As_ = sm + (s) * 2 * TILE_WORDS;                                \
        float* Bs_ = As_ + TILE_WORDS;                                         \
        const float* Ag_ = A + (size_t)(m0) * K + (kt) * 32;                   \
        const float* Bg_ = B + (size_t)(n0) * K + (kt) * 32;                   \
        _Pragma("unroll")                                                      \
        for (int p_ = 0; p_ < 4; p_++) {                                       \
            int r_ = p_ * 32 + lr;                                             \
            cpa16(smem_u32(&As_[r_ * TILE_W + lc]), Ag_ + (size_t)r_ * K + lc);\
            cpa16(smem_u32(&Bs_[r_ * TILE_W + lc]), Bg_ + (size_t)r_ * K + lc);\
        }                                                                      \
    } while (0)

    const int NT = K >> 5;
    PREFETCH(0, 0);
    CP_COMMIT();

    for (int kt = 0; kt < NT; kt++) {
        const int s = kt & 1;
        if (kt + 1 < NT) {
            PREFETCH(kt + 1, s ^ 1);
            CP_COMMIT();
            CP_WAIT(1);
        } else {
            CP_WAIT(0);
        }
        __syncthreads();

        const uint32_t* Asu = (const uint32_t*)(sm + s * 2 * TILE_WORDS);
        const uint32_t* Bsu = Asu + TILE_WORDS;
#pragma unroll
        for (int ks = 0; ks < 4; ks++) {
            const int k = ks * 8;
            uint32_t af[4][4], bf[4][2];
#pragma unroll
            for (int mt = 0; mt < 4; mt++) {
                int rb = wm + mt * 16 + g;
                af[mt][0] = Asu[rb * TILE_W + k + th];
                af[mt][1] = Asu[(rb + 8) * TILE_W + k + th];
                af[mt][2] = Asu[rb * TILE_W + k + th + 4];
                af[mt][3] = Asu[(rb + 8) * TILE_W + k + th + 4];
            }
#pragma unroll
            for (int nt = 0; nt < 4; nt++) {
                int rb = wn + nt * 8 + g;
                bf[nt][0] = Bsu[rb * TILE_W + k + th];
                bf[nt][1] = Bsu[rb * TILE_W + k + th + 4];
            }
#pragma unroll
            for (int mt = 0; mt < 4; mt++)
#pragma unroll
                for (int nt = 0; nt < 4; nt++) {
                    asm volatile(
                        "mma.sync.aligned.m16n8k8.row.col.f32.tf32.tf32.f32 "
                        "{%0,%1,%2,%3}, {%4,%5,%6,%7}, {%8,%9}, {%0,%1,%2,%3};"
                        : "+f"(acc[mt][nt][0]), "+f"(acc[mt][nt][1]),
                          "+f"(acc[mt][nt][2]), "+f"(acc[mt][nt][3])
                        : "r"(af[mt][0]), "r"(af[mt][1]), "r"(af[mt][2]), "r"(af[mt][3]),
                          "r"(bf[nt][0]), "r"(bf[nt][1]));
                }
        }
        __syncthreads();
    }
#undef PREFETCH

    // epilogue: direct float2 stores (+bias)
#pragma unroll
    for (int mt = 0; mt < 4; mt++) {
        const int row = m0 + wm + mt * 16 + g;
#pragma unroll
        for (int nt = 0; nt < 4; nt++) {
            const int col = n0 + wn + nt * 8 + 2 * th;
            float2 v0 = make_float2(acc[mt][nt][0], acc[mt][nt][1]);
            float2 v1 = make_float2(acc[mt][nt][2], acc[mt][nt][3]);
            if (bias) {
                float b0 = bias[col], b1 = bias[col + 1];
                v0.x += b0; v0.y += b1; v1.x += b0; v1.y += b1;
            }
            *(float2*)&C[(size_t)row * ldc + col]       = v0;
            *(float2*)&C[(size_t)(row + 8) * ldc + col] = v1;
        }
    }
}

// ---------------- fused flash attention with relative-position skew ----------------
#define QT_S 68
#define KT_S 68
#define VS_S 68
#define SS_S 68
#define ER_S 132
#define RED_S 17
#define FLASH_SMEM_FLOATS (64*QT_S + 64*KT_S + 64*VS_S + 64*ER_S + 64*SS_S + 64*RED_S + 3*64)
#define FLASH_SMEM_BYTES  (FLASH_SMEM_FLOATS * 4)

__global__ __launch_bounds__(256, 2)
void flash_kernel(const float* __restrict__ qkv, const float* __restrict__ Er,
                  float* __restrict__ attn)
{
    extern __shared__ __align__(16) float sm[];
    float* Qt    = sm;
    float* Kt    = Qt  + 64*QT_S;
    float* Vs    = Kt  + 64*KT_S;
    float* ErT   = Vs  + 64*VS_S;
    float* Ss    = ErT + 64*ER_S;
    float* red   = Ss  + 64*SS_S;
    float* rowM  = red + 64*RED_S;
    float* rowL  = rowM + 64;
    float* rowSc = rowL + 64;

    const int z  = blockIdx.y;
    const int b  = z >> 4, h = z & 15;
    const int i0 = (int)(gridDim.x - 1 - blockIdx.x) * 64;
    const int tid = threadIdx.x;
    const int tx = tid & 15, ty = tid >> 4;
    const int RS = 3 * DIMC;

    const float* qb = qkv + (size_t)b * SEQ * RS + h * HD;
    const float* kb = qb + DIMC;
    const float* vb = qb + 2 * DIMC;

#pragma unroll
    for (int s = 0; s < 4; s++) {
        int vv = tid + 256 * s;
        int ln = vv & 63, dq = (vv >> 6) << 2;
        float4 t = *(const float4*)&qb[(size_t)(i0 + ln) * RS + dq];
        Qt[(dq+0)*QT_S + ln] = t.x; Qt[(dq+1)*QT_S + ln] = t.y;
        Qt[(dq+2)*QT_S + ln] = t.z; Qt[(dq+3)*QT_S + ln] = t.w;
    }
    if (tid < 64) { rowM[tid] = -1e30f; rowL[tid] = 0.0f; }

    ull o2[4][2];
#pragma unroll
    for (int i = 0; i < 4; i++) { o2[i][0] = 0ull; o2[i][1] = 0ull; }

    const int ntiles = i0 / 64 + 1;
    for (int kt = 0; kt < ntiles; kt++) {
        const int kt0 = kt * 64;
        __syncthreads();

#pragma unroll
        for (int s = 0; s < 4; s++) {
            int vv = tid + 256 * s;
            int ln = vv & 63, dq = (vv >> 6) << 2;
            float4 t = *(const float4*)&kb[(size_t)(kt0 + ln) * RS + dq];
            Kt[(dq+0)*KT_S + ln] = t.x; Kt[(dq+1)*KT_S + ln] = t.y;
            Kt[(dq+2)*KT_S + ln] = t.z; Kt[(dq+3)*KT_S + ln] = t.w;
            int lm = vv >> 4, dv = (vv & 15) << 2;
            float4 u = *(const float4*)&vb[(size_t)(kt0 + lm) * RS + dv];
            *(float4*)&Vs[lm * VS_S + dv] = u;
        }
        const int j0 = SEQ - 64 - i0 + kt0;
#pragma unroll
        for (int s = 0; s < 8; s++) {
            int vv = tid + 256 * s;
            int jl = vv & 127, dq = (vv >> 7) << 2;
            int j = j0 + jl;
            float4 t = make_float4(0.f, 0.f, 0.f, 0.f);
            if (j < SEQ) t = *(const float4*)&Er[(size_t)j * HD + dq];
            ErT[(dq+0)*ER_S + jl] = t.x; ErT[(dq+1)*ER_S + jl] = t.y;
            ErT[(dq+2)*ER_S + jl] = t.z; ErT[(dq+3)*ER_S + jl] = t.w;
        }
        __syncthreads();

        ull  c2[4][2];
        float rel[4][4];
#pragma unroll
        for (int i = 0; i < 4; i++) {
            c2[i][0] = 0ull; c2[i][1] = 0ull;
#pragma unroll
            for (int j = 0; j < 4; j++) rel[i][j] = 0.0f;
        }
        const int ebase = 4*tx - 4*ty + 60;
#pragma unroll 4
        for (int kk = 0; kk < 64; kk++) {
            float a[4];
            *(float4*)&a[0] = *(const float4*)&Qt[kk * QT_S + 4*ty];
            ull b0 = *(const ull*)&Kt[kk * KT_S + 4*tx];
            ull b1 = *(const ull*)&Kt[kk * KT_S + 4*tx + 2];
            float e[8];
            *(float4*)&e[0] = *(const float4*)&ErT[kk * ER_S + ebase];
            *(float4*)&e[4] = *(const float4*)&ErT[kk * ER_S + ebase + 4];
#pragma unroll
            for (int i = 0; i < 4; i++) {
                ull a2 = dup2(a[i]);
                c2[i][0] = fma2(a2, b0, c2[i][0]);
                c2[i][1] = fma2(a2, b1, c2[i][1]);
#pragma unroll
                for (int j = 0; j < 4; j++)
                    rel[i][j] += a[i] * e[j - i + 3];
            }
        }

        float sv[4][4];
#pragma unroll
        for (int i = 0; i < 4; i++) {
            const int n = i0 + 4*ty + i;
            float2 p0 = unpack2(c2[i][0]), p1 = unpack2(c2[i][1]);
            sv[i][0] = p0.x + rel[i][0]; sv[i][1] = p0.y + rel[i][1];
            sv[i][2] = p1.x + rel[i][2]; sv[i][3] = p1.y + rel[i][3];
            float mx = -1e30f;
#pragma unroll
            for (int j = 0; j < 4; j++) {
                int m = kt0 + 4*tx + j;
                sv[i][j] = (m <= n) ? sv[i][j] * 0.125f : -1e30f;
                mx = fmaxf(mx, sv[i][j]);
            }
            red[(4*ty + i) * RED_S + tx] = mx;
        }
        __syncthreads();
        if (tid < 64) {
            float tm = -1e30f;
#pragma unroll
            for (int t = 0; t < 16; t++) tm = fmaxf(tm, red[tid * RED_S + t]);
            float om = rowM[tid];
            float nm = fmaxf(om, tm);
            rowSc[tid] = __expf(om - nm);
            rowM[tid]  = nm;
        }
        __syncthreads();

#pragma unroll
        for (int i = 0; i < 4; i++) {
            const int r = 4*ty + i;
            const float mrow = rowM[r];
            float ps = 0.0f;
#pragma unroll
            for (int j = 0; j < 4; j++) {
                float p = __expf(sv[i][j] - mrow);
                ps += p;
                Ss[r * SS_S + 4*tx + j] = p;
            }
            red[r * RED_S + tx] = ps;
        }
        __syncthreads();
        if (tid < 64) {
            float s = 0.0f;
#pragma unroll
            for (int t = 0; t < 16; t++) s += red[tid * RED_S + t];
            rowL[tid] = rowL[tid] * rowSc[tid] + s;
        }

#pragma unroll
        for (int i = 0; i < 4; i++) {
            ull sc = dup2(rowSc[4*ty + i]);
            o2[i][0] = mul2(o2[i][0], sc);
            o2[i][1] = mul2(o2[i][1], sc);
        }
#pragma unroll 4
        for (int m = 0; m < 64; m++) {
            ull b0 = *(const ull*)&Vs[m * VS_S + 4*tx];
            ull b1 = *(const ull*)&Vs[m * VS_S + 4*tx + 2];
#pragma unroll
            for (int i = 0; i < 4; i++) {
                ull a2 = dup2(Ss[(4*ty + i) * SS_S + m]);
                o2[i][0] = fma2(a2, b0, o2[i][0]);
                o2[i][1] = fma2(a2, b1, o2[i][1]);
            }
        }
    }
    __syncthreads();

#pragma unroll
    for (int i = 0; i < 4; i++) {
        const int n = i0 + 4*ty + i;
        const float inv = 1.0f / rowL[4*ty + i];
        float2 p0 = unpack2(o2[i][0]), p1 = unpack2(o2[i][1]);
        float* dst = attn + ((size_t)b * SEQ + n) * DIMC + h * HD + 4*tx;
        dst[0] = p0.x * inv; dst[1] = p0.y * inv;
        dst[2] = p1.x * inv; dst[3] = p1.y * inv;
    }
}

// ---------------- launch ----------------
extern "C" void kernel_launch(void* const* d_in, const int* in_sizes, int n_in,
                              void* d_out, int out_size)
{
    const float* x     = (const float*)d_in[0];
    const float* Wqkv  = (const float*)d_in[1];
    const float* Wproj = (const float*)d_in[2];
    const float* bproj = (const float*)d_in[3];
    const float* Er    = (const float*)d_in[4];
    float* out = (float*)d_out;

    float *qkv, *attn, *xt, *wqkvt, *attnt, *wprojt;
    cudaGetSymbolAddress((void**)&qkv,    g_qkv);
    cudaGetSymbolAddress((void**)&attn,   g_attn);
    cudaGetSymbolAddress((void**)&xt,     g_xt);
    cudaGetSymbolAddress((void**)&wqkvt,  g_wqkvt);
    cudaGetSymbolAddress((void**)&attnt,  g_attnt);
    cudaGetSymbolAddress((void**)&wprojt, g_wprojt);

    cudaFuncSetAttribute(tf32_gemm, cudaFuncAttributeMaxDynamicSharedMemorySize, GSMEM_BYTES);
    cudaFuncSetAttribute(flash_kernel, cudaFuncAttributeMaxDynamicSharedMemorySize, FLASH_SMEM_BYTES);

    // 1) round inputs to tf32 (rna) so mma truncation bias is avoided
    conv_tf32<<<(BATCH*SEQ*DIMC/4 + 255)/256, 256>>>(x,    xt,    BATCH*SEQ*DIMC);
    conv_tf32<<<(3*DIMC*DIMC/4   + 255)/256, 256>>>(Wqkv, wqkvt, 3*DIMC*DIMC);

    // 2) qkv = x @ Wqkv^T  (M=4096, N=3072, K=1024) via tf32 mma.sync
    tf32_gemm<<<dim3(32, 24), 256, GSMEM_BYTES>>>(xt, wqkvt, qkv, nullptr, DIMC, 3*DIMC);

    // 3) fused attention (content + rel-skew + causal softmax + P@V)
    flash_kernel<<<dim3(16, 64), 256, FLASH_SMEM_BYTES>>>(qkv, Er, attn);

    // 4) round attn / Wproj, then out = attn @ Wproj^T + b  (M=4096, N=1024, K=1024)
    conv_tf32<<<(BATCH*SEQ*DIMC/4 + 255)/256, 256>>>(attn,  attnt,  BATCH*SEQ*DIMC);
    conv_tf32<<<(DIMC*DIMC/4     + 255)/256, 256>>>(Wproj, wprojt, DIMC*DIMC);
    tf32_gemm<<<dim3(32, 8), 256, GSMEM_BYTES>>>(attnt, wprojt, out, bproj, DIMC, DIMC);
}

// round 7
// speedup vs baseline: 6.6603x; 1.9587x over previous
#include <cuda_runtime.h>
#include <cstdint>

#define BATCH 4
#define SEQ   1024
#define DIMC  1024
#define HEADS 16
#define HD    64

// ---------------- helpers ----------------
__device__ __forceinline__ uint32_t smem_u32(const void* p) {
    uint32_t a;
    asm("{ .reg .u64 t; cvta.to.shared.u64 t, %1; cvt.u32.u64 %0, t; }" : "=r"(a) : "l"(p));
    return a;
}
__device__ __forceinline__ void cpa16(uint32_t dst, const void* src) {
    asm volatile("cp.async.cg.shared.global [%0], [%1], 16;" :: "r"(dst), "l"(src));
}
#define CP_COMMIT() asm volatile("cp.async.commit_group;" ::: "memory")
#define CP_WAIT(n)  asm volatile("cp.async.wait_group %0;" :: "n"(n) : "memory")

__device__ __forceinline__ uint32_t rna(float f) {
    uint32_t r; asm("cvt.rna.tf32.f32 %0, %1;" : "=r"(r) : "f"(f)); return r;
}

#define MMA_TF32(acc, a0, a1, a2, a3, b0, b1) \
    asm volatile("mma.sync.aligned.m16n8k8.row.col.f32.tf32.tf32.f32 " \
        "{%0,%1,%2,%3}, {%4,%5,%6,%7}, {%8,%9}, {%0,%1,%2,%3};" \
        : "+f"((acc)[0]), "+f"((acc)[1]), "+f"((acc)[2]), "+f"((acc)[3]) \
        : "r"(a0), "r"(a1), "r"(a2), "r"(a3), "r"(b0), "r"(b1))

// ---------------- scratch ----------------
__device__ __align__(16) float g_qkv  [(size_t)BATCH*SEQ*3*DIMC];   // 50 MB fp32
__device__ __align__(16) float g_xt   [(size_t)BATCH*SEQ*DIMC];     // tf32-rounded
__device__ __align__(16) float g_wqkvt[(size_t)3*DIMC*DIMC];
__device__ __align__(16) float g_attnt[(size_t)BATCH*SEQ*DIMC];     // flash writes tf32-rounded
__device__ __align__(16) float g_wprojt[(size_t)DIMC*DIMC];

// ---------------- round fp32 -> tf32 (rna) elementwise ----------------
__global__ void conv_tf32(const float* __restrict__ in, float* __restrict__ out, int total)
{
    int i = (blockIdx.x * blockDim.x + threadIdx.x) * 4;
    if (i >= total) return;
    float4 v = *(const float4*)(in + i);
    uint4 o = { rna(v.x), rna(v.y), rna(v.z), rna(v.w) };
    *(uint4*)(out + i) = o;
}

// ---------------- tf32 mma.sync GEMM (unchanged from R6) ----------------
#define TILE_W 36
#define TILE_WORDS (128*TILE_W)
#define GSMEM_BYTES (2*2*TILE_WORDS*4)

__global__ __launch_bounds__(256, 2)
void tf32_gemm(const float* __restrict__ A, const float* __restrict__ B,
               float* __restrict__ C, const float* __restrict__ bias, int K, int ldc)
{
    extern __shared__ __align__(16) float sm[];
    const int tid = threadIdx.x, w = tid >> 5, t = tid & 31;
    const int m0 = blockIdx.x * 128, n0 = blockIdx.y * 128;
    const int wm = (w >> 2) * 64, wn = (w & 3) * 32;
    const int g = t >> 2, th = t & 3;

    float acc[4][4][4];
#pragma unroll
    for (int mt = 0; mt < 4; mt++)
#pragma unroll
        for (int nt = 0; nt < 4; nt++)
#pragma unroll
            for (int r = 0; r < 4; r++) acc[mt][nt][r] = 0.0f;

    const int lr = tid >> 3;
    const int lc = (tid & 7) << 2;

#define PREFETCH(kt, s) do {                                                   \
        float* As_ = sm + (s) * 2 * TILE_WORDS;                                \
        float* Bs_ = As_ + TILE_WORDS;                                         \
        const float* Ag_ = A + (size_t)(m0) * K + (kt) * 32;                   \
        const float* Bg_ = B + (size_t)(n0) * K + (kt) * 32;                   \
        _Pragma("unroll")                                                      \
        for (int p_ = 0; p_ < 4; p_++) {                                       \
            int r_ = p_ * 32 + lr;                                             \
            cpa16(smem_u32(&As_[r_ * TILE_W + lc]), Ag_ + (size_t)r_ * K + lc);\
            cpa16(smem_u32(&Bs_[r_ * TILE_W + lc]), Bg_ + (size_t)r_ * K + lc);\
        }                                                                      \
    } while (0)

    const int NT = K >> 5;
    PREFETCH(0, 0);
    CP_COMMIT();

    for (int kt = 0; kt < NT; kt++) {
        const int s = kt & 1;
        if (kt + 1 < NT) { PREFETCH(kt + 1, s ^ 1); CP_COMMIT(); CP_WAIT(1); }
        else             { CP_WAIT(0); }
        __syncthreads();

        const uint32_t* Asu = (const uint32_t*)(sm + s * 2 * TILE_WORDS);
        const uint32_t* Bsu = Asu + TILE_WORDS;
#pragma unroll
        for (int ks = 0; ks < 4; ks++) {
            const int k = ks * 8;
            uint32_t af[4][4], bf[4][2];
#pragma unroll
            for (int mt = 0; mt < 4; mt++) {
                int rb = wm + mt * 16 + g;
                af[mt][0] = Asu[rb * TILE_W + k + th];
                af[mt][1] = Asu[(rb + 8) * TILE_W + k + th];
                af[mt][2] = Asu[rb * TILE_W + k + th + 4];
                af[mt][3] = Asu[(rb + 8) * TILE_W + k + th + 4];
            }
#pragma unroll
            for (int nt = 0; nt < 4; nt++) {
                int rb = wn + nt * 8 + g;
                bf[nt][0] = Bsu[rb * TILE_W + k + th];
                bf[nt][1] = Bsu[rb * TILE_W + k + th + 4];
            }
#pragma unroll
            for (int mt = 0; mt < 4; mt++)
#pragma unroll
                for (int nt = 0; nt < 4; nt++)
                    MMA_TF32(acc[mt][nt], af[mt][0], af[mt][1], af[mt][2], af[mt][3],
                             bf[nt][0], bf[nt][1]);
        }
        __syncthreads();
    }
#undef PREFETCH

#pragma unroll
    for (int mt = 0; mt < 4; mt++) {
        const int row = m0 + wm + mt * 16 + g;
#pragma unroll
        for (int nt = 0; nt < 4; nt++) {
            const int col = n0 + wn + nt * 8 + 2 * th;
            float2 v0 = make_float2(acc[mt][nt][0], acc[mt][nt][1]);
            float2 v1 = make_float2(acc[mt][nt][2], acc[mt][nt][3]);
            if (bias) {
                float b0 = bias[col], b1 = bias[col + 1];
                v0.x += b0; v0.y += b1; v1.x += b0; v1.y += b1;
            }
            *(float2*)&C[(size_t)row * ldc + col]       = v0;
            *(float2*)&C[(size_t)(row + 8) * ldc + col] = v1;
        }
    }
}

// ---------------- flash2: tensor-core flash attention with rel skew ----------------
// CTA: 128 q-rows x 64-kv tiles. 8 warps, warp w owns q rows [16w,16w+16).
// rel[n,m] = q_n . Er[1023-(n-m)]; per warp an 80-wide banded R-GEMM vs a 192-row
// Er window; gather rel[r,c] = R[r, r-c+64] via per-warp smem staging.
#define FL_SMEM_FLOATS (64*68 + 64*68 + 192*68 + 8*16*84)
#define FL_SMEM_BYTES  (FL_SMEM_FLOATS * 4)   // 130048

__global__ __launch_bounds__(256, 1)
void flash2_kernel(const float* __restrict__ qkv, const float* __restrict__ Er,
                   float* __restrict__ attn)
{
    extern __shared__ __align__(16) float sm[];
    float* Ksm = sm;                  // 64 x 68
    float* Vsm = Ksm + 64*68;         // 64 x 68
    float* Esm = Vsm + 64*68;         // 192 x 68
    float* Rst = Esm + 192*68;        // 8 warps x 16 x 84 (also Q staging)

    const int tid = threadIdx.x;
    const int w = tid >> 5, lane = tid & 31;
    const int qr = lane >> 2, qc = lane & 3;
    const int z = blockIdx.x;
    const int b = z >> 4, h = z & 15;
    const int i0 = (7 - (int)blockIdx.y) * 128;   // heavy q-tiles first
    const int ntiles = (i0 >> 6) + 2;

    const float* qg = qkv + (size_t)b * SEQ * (3*DIMC) + h * HD;
    const float* kg = qg + DIMC;
    const float* vg = qg + 2*DIMC;

    const uint32_t* Ku = (const uint32_t*)Ksm;
    const uint32_t* Vu = (const uint32_t*)Vsm;
    const uint32_t* Eu = (const uint32_t*)Esm;
    float*    Rwf = Rst + w * (16*84);
    uint32_t* Pw  = (uint32_t*)Rwf;   // P staging reuses R region (stride 68)

    // ---- stage Q (tf32) then load persistent A-frags ----
    {
        uint32_t* Qs = (uint32_t*)Rst;
#pragma unroll
        for (int s = 0; s < 8; s++) {
            int idx = tid + (s << 8);
            int row = idx >> 4, c4 = (idx & 15) << 2;
            float4 t = *(const float4*)&qg[(size_t)(i0 + row) * (3*DIMC) + c4];
            uint4 o = { rna(t.x), rna(t.y), rna(t.z), rna(t.w) };
            *(uint4*)&Qs[row * 68 + c4] = o;
        }
    }
    __syncthreads();
    uint32_t qa[8][4];
    {
        const uint32_t* Qs = (const uint32_t*)Rst;
        const int base = (16*w + qr) * 68 + qc;
#pragma unroll
        for (int ks = 0; ks < 8; ks++) {
            qa[ks][0] = Qs[base + 8*ks];
            qa[ks][1] = Qs[base + 8*68 + 8*ks];
            qa[ks][2] = Qs[base + 8*ks + 4];
            qa[ks][3] = Qs[base + 8*68 + 8*ks + 4];
        }
    }
    __syncthreads();

    float oa[8][4];
#pragma unroll
    for (int nf = 0; nf < 8; nf++) { oa[nf][0]=0.f; oa[nf][1]=0.f; oa[nf][2]=0.f; oa[nf][3]=0.f; }
    float mA = -1e30f, mB = -1e30f, lA = 0.f, lB = 0.f;
    const int rowA = i0 + 16*w + qr;
    const int rowB = rowA + 8;
    const float SC = 0.18033688011112042f;   // 0.125 * log2(e)

    for (int kt = 0; kt < ntiles; kt++) {
        const int kt0 = kt << 6;
        __syncthreads();   // guard V/K/E reuse across iterations

        // K & V tiles (tf32-rounded)
#pragma unroll
        for (int s = 0; s < 4; s++) {
            int idx = tid + (s << 8);
            int row = idx >> 4, c4 = (idx & 15) << 2;
            float4 t = *(const float4*)&kg[(size_t)(kt0 + row) * (3*DIMC) + c4];
            uint4 ok = { rna(t.x), rna(t.y), rna(t.z), rna(t.w) };
            *(uint4*)&((uint32_t*)Ksm)[row*68 + c4] = ok;
            t = *(const float4*)&vg[(size_t)(kt0 + row) * (3*DIMC) + c4];
            uint4 ov = { rna(t.x), rna(t.y), rna(t.z), rna(t.w) };
            *(uint4*)&((uint32_t*)Vsm)[row*68 + c4] = ov;
        }
        // Er window: row jw -> Er[1087 - i0 + kt0 - jw]  (clamped; invalid rows masked later)
        const int ebase = 1087 - i0 + kt0;
#pragma unroll
        for (int s = 0; s < 12; s++) {
            int idx = tid + (s << 8);
            int row = idx >> 4, c4 = (idx & 15) << 2;
            int ei = ebase - row;
            ei = ei < 0 ? 0 : (ei > 1023 ? 1023 : ei);
            float4 t = *(const float4*)&Er[(size_t)ei * HD + c4];
            uint4 oe = { rna(t.x), rna(t.y), rna(t.z), rna(t.w) };
            *(uint4*)&((uint32_t*)Esm)[row*68 + c4] = oe;
        }
        __syncthreads();

        // ---- S = Q K^T ----
        float sacc[8][4];
#pragma unroll
        for (int nf = 0; nf < 8; nf++) { sacc[nf][0]=0.f; sacc[nf][1]=0.f; sacc[nf][2]=0.f; sacc[nf][3]=0.f; }
#pragma unroll
        for (int ks = 0; ks < 8; ks++)
#pragma unroll
            for (int nf = 0; nf < 8; nf++) {
                uint32_t b0 = Ku[(8*nf + qr)*68 + 8*ks + qc];
                uint32_t b1 = Ku[(8*nf + qr)*68 + 8*ks + qc + 4];
                MMA_TF32(sacc[nf], qa[ks][0], qa[ks][1], qa[ks][2], qa[ks][3], b0, b1);
            }

        // ---- R = Q E'^T (80-wide banded window, per warp rows [16w,16w+80)) ----
        float racc[10][4];
#pragma unroll
        for (int j = 0; j < 10; j++) { racc[j][0]=0.f; racc[j][1]=0.f; racc[j][2]=0.f; racc[j][3]=0.f; }
#pragma unroll
        for (int ks = 0; ks < 8; ks++)
#pragma unroll
            for (int j = 0; j < 10; j++) {
                uint32_t b0 = Eu[(16*w + 8*j + qr)*68 + 8*ks + qc];
                uint32_t b1 = Eu[(16*w + 8*j + qr)*68 + 8*ks + qc + 4];
                MMA_TF32(racc[j], qa[ks][0], qa[ks][1], qa[ks][2], qa[ks][3], b0, b1);
            }
        // stage R to per-warp smem
#pragma unroll
        for (int j = 0; j < 10; j++) {
            int cb = 8*j + 2*qc;
            Rwf[qr*84 + cb]         = racc[j][0];
            Rwf[qr*84 + cb + 1]     = racc[j][1];
            Rwf[(qr+8)*84 + cb]     = racc[j][2];
            Rwf[(qr+8)*84 + cb + 1] = racc[j][3];
        }
        __syncwarp();

        // ---- combine + mask (log2-scaled scores into sacc) ----
#pragma unroll
        for (int nf = 0; nf < 8; nf++) {
            int c0 = 8*nf + 2*qc;
            int jA = qr - c0 + 64;          // in [2,71]
            float rA0 = Rwf[qr*84 + jA];
            float rA1 = Rwf[qr*84 + jA - 1];
            float rB0 = Rwf[(qr+8)*84 + jA + 8];
            float rB1 = Rwf[(qr+8)*84 + jA + 7];
            int mg = kt0 + c0;
            sacc[nf][0] = (mg     <= rowA) ? (sacc[nf][0] + rA0) * SC : -1e30f;
            sacc[nf][1] = (mg + 1 <= rowA) ? (sacc[nf][1] + rA1) * SC : -1e30f;
            sacc[nf][2] = (mg     <= rowB) ? (sacc[nf][2] + rB0) * SC : -1e30f;
            sacc[nf][3] = (mg + 1 <= rowB) ? (sacc[nf][3] + rB1) * SC : -1e30f;
        }

        // ---- online softmax (rows fully in-warp; quad shfl reduce) ----
        float tmA = -1e30f, tmB = -1e30f;
#pragma unroll
        for (int nf = 0; nf < 8; nf++) {
            tmA = fmaxf(tmA, fmaxf(sacc[nf][0], sacc[nf][1]));
            tmB = fmaxf(tmB, fmaxf(sacc[nf][2], sacc[nf][3]));
        }
        tmA = fmaxf(tmA, __shfl_xor_sync(0xffffffffu, tmA, 1));
        tmA = fmaxf(tmA, __shfl_xor_sync(0xffffffffu, tmA, 2));
        tmB = fmaxf(tmB, __shfl_xor_sync(0xffffffffu, tmB, 1));
        tmB = fmaxf(tmB, __shfl_xor_sync(0xffffffffu, tmB, 2));
        float nmA = fmaxf(mA, tmA), nmB = fmaxf(mB, tmB);
        float aAs = exp2f(mA - nmA), aBs = exp2f(mB - nmB);
        mA = nmA; mB = nmB;

        float sA = 0.f, sB = 0.f;
#pragma unroll
        for (int nf = 0; nf < 8; nf++) {
            sacc[nf][0] = exp2f(sacc[nf][0] - mA);
            sacc[nf][1] = exp2f(sacc[nf][1] - mA);
            sacc[nf][2] = exp2f(sacc[nf][2] - mB);
            sacc[nf][3] = exp2f(sacc[nf][3] - mB);
            sA += sacc[nf][0] + sacc[nf][1];
            sB += sacc[nf][2] + sacc[nf][3];
            oa[nf][0] *= aAs; oa[nf][1] *= aAs;
            oa[nf][2] *= aBs; oa[nf][3] *= aBs;
        }
        sA += __shfl_xor_sync(0xffffffffu, sA, 1);
        sA += __shfl_xor_sync(0xffffffffu, sA, 2);
        sB += __shfl_xor_sync(0xffffffffu, sB, 1);
        sB += __shfl_xor_sync(0xffffffffu, sB, 2);
        lA = lA * aAs + sA;
        lB = lB * aBs + sB;

        __syncwarp();   // R reads done before P overwrites region
#pragma unroll
        for (int nf = 0; nf < 8; nf++) {
            int c0 = 8*nf + 2*qc;
            Pw[qr*68 + c0]         = rna(sacc[nf][0]);
            Pw[qr*68 + c0 + 1]     = rna(sacc[nf][1]);
            Pw[(qr+8)*68 + c0]     = rna(sacc[nf][2]);
            Pw[(qr+8)*68 + c0 + 1] = rna(sacc[nf][3]);
        }
        __syncwarp();

        // ---- O += P V ----
#pragma unroll
        for (int ks = 0; ks < 8; ks++) {
            uint32_t p0 = Pw[qr*68 + 8*ks + qc];
            uint32_t p1 = Pw[(qr+8)*68 + 8*ks + qc];
            uint32_t p2 = Pw[qr*68 + 8*ks + qc + 4];
            uint32_t p3 = Pw[(qr+8)*68 + 8*ks + qc + 4];
#pragma unroll
            for (int nf = 0; nf < 8; nf++) {
                uint32_t b0 = Vu[(8*ks + qc)*68 + 8*nf + qr];
                uint32_t b1 = Vu[(8*ks + qc + 4)*68 + 8*nf + qr];
                MMA_TF32(oa[nf], p0, p1, p2, p3, b0, b1);
            }
        }
    }

    // ---- epilogue: normalize, round to tf32 for the proj GEMM, store ----
    const float invA = 1.f / lA, invB = 1.f / lB;
#pragma unroll
    for (int nf = 0; nf < 8; nf++) {
        int d = h*HD + 8*nf + 2*qc;
        uint2 vA = { rna(oa[nf][0]*invA), rna(oa[nf][1]*invA) };
        uint2 vB = { rna(oa[nf][2]*invB), rna(oa[nf][3]*invB) };
        *(uint2*)&attn[((size_t)b*SEQ + rowA)*DIMC + d] = vA;
        *(uint2*)&attn[((size_t)b*SEQ + rowB)*DIMC + d] = vB;
    }
}

// ---------------- launch ----------------
extern "C" void kernel_launch(void* const* d_in, const int* in_sizes, int n_in,
                              void* d_out, int out_size)
{
    const float* x     = (const float*)d_in[0];
    const float* Wqkv  = (const float*)d_in[1];
    const float* Wproj = (const float*)d_in[2];
    const float* bproj = (const float*)d_in[3];
    const float* Er    = (const float*)d_in[4];
    float* out = (float*)d_out;

    float *qkv, *xt, *wqkvt, *attnt, *wprojt;
    cudaGetSymbolAddress((void**)&qkv,    g_qkv);
    cudaGetSymbolAddress((void**)&xt,     g_xt);
    cudaGetSymbolAddress((void**)&wqkvt,  g_wqkvt);
    cudaGetSymbolAddress((void**)&attnt,  g_attnt);
    cudaGetSymbolAddress((void**)&wprojt, g_wprojt);

    cudaFuncSetAttribute(tf32_gemm, cudaFuncAttributeMaxDynamicSharedMemorySize, GSMEM_BYTES);
    cudaFuncSetAttribute(flash2_kernel, cudaFuncAttributeMaxDynamicSharedMemorySize, FL_SMEM_BYTES);

    // 1) tf32-round x and Wqkv
    conv_tf32<<<(BATCH*SEQ*DIMC/4 + 255)/256, 256>>>(x,    xt,    BATCH*SEQ*DIMC);
    conv_tf32<<<(3*DIMC*DIMC/4   + 255)/256, 256>>>(Wqkv, wqkvt, 3*DIMC*DIMC);

    // 2) qkv = x @ Wqkv^T  (M=4096, N=3072, K=1024)
    tf32_gemm<<<dim3(32, 24), 256, GSMEM_BYTES>>>(xt, wqkvt, qkv, nullptr, DIMC, 3*DIMC);

    // 3) tensor-core flash attention (writes tf32-rounded attn)
    flash2_kernel<<<dim3(64, 8), 256, FL_SMEM_BYTES>>>(qkv, Er, attnt);

    // 4) out = attn @ Wproj^T + b  (M=4096, N=1024, K=1024)
    conv_tf32<<<(DIMC*DIMC/4 + 255)/256, 256>>>(Wproj, wprojt, DIMC*DIMC);
    tf32_gemm<<<dim3(32, 8), 256, GSMEM_BYTES>>>(attnt, wprojt, out, bproj, DIMC, DIMC);
}

// round 8
// speedup vs baseline: 10.9670x; 1.6466x over previous
#include <cuda_runtime.h>
#include <cuda_fp16.h>
#include <cstdint>

#define BATCH 4
#define SEQ   1024
#define DIMC  1024
#define HEADS 16
#define HD    64

// ---------------- helpers ----------------
__device__ __forceinline__ uint32_t smem_u32(const void* p) {
    uint32_t a;
    asm("{ .reg .u64 t; cvta.to.shared.u64 t, %1; cvt.u32.u64 %0, t; }" : "=r"(a) : "l"(p));
    return a;
}
__device__ __forceinline__ void cpa16(uint32_t dst, const void* src) {
    asm volatile("cp.async.cg.shared.global [%0], [%1], 16;" :: "r"(dst), "l"(src));
}
#define CP_COMMIT() asm volatile("cp.async.commit_group;" ::: "memory")
#define CP_WAIT(n)  asm volatile("cp.async.wait_group %0;" :: "n"(n) : "memory")

#define MMA_F16(acc, a0, a1, a2, a3, b0, b1) \
    asm volatile("mma.sync.aligned.m16n8k16.row.col.f32.f16.f16.f32 " \
        "{%0,%1,%2,%3}, {%4,%5,%6,%7}, {%8,%9}, {%0,%1,%2,%3};" \
        : "+f"((acc)[0]), "+f"((acc)[1]), "+f"((acc)[2]), "+f"((acc)[3]) \
        : "r"(a0), "r"(a1), "r"(a2), "r"(a3), "r"(b0), "r"(b1))

__device__ __forceinline__ uint32_t pkh2(float lo, float hi) {
    __half2 h = __float22half2_rn(make_float2(lo, hi));
    return *(uint32_t*)&h;
}

// ---------------- scratch (fp16) ----------------
__device__ __align__(16) __half g_qkvh [(size_t)BATCH*SEQ*3*DIMC];  // 25 MB
__device__ __align__(16) __half g_xh   [(size_t)BATCH*SEQ*DIMC];
__device__ __align__(16) __half g_wqkvh[(size_t)3*DIMC*DIMC];
__device__ __align__(16) __half g_wprojh[(size_t)DIMC*DIMC];
__device__ __align__(16) __half g_erh  [(size_t)SEQ*HD];
__device__ __align__(16) __half g_attnh[(size_t)BATCH*SEQ*DIMC];

// ---------------- fp32 -> fp16 elementwise ----------------
__global__ void conv_h16(const float* __restrict__ in, __half* __restrict__ out, int total)
{
    int i = (blockIdx.x * blockDim.x + threadIdx.x) * 8;
    if (i >= total) return;
    float4 v0 = *(const float4*)(in + i);
    float4 v1 = *(const float4*)(in + i + 4);
    uint4 o = { pkh2(v0.x, v0.y), pkh2(v0.z, v0.w), pkh2(v1.x, v1.y), pkh2(v1.z, v1.w) };
    *(uint4*)((__half*)out + i) = o;
}

// ---------------- fp16 mma.sync GEMM: C[m,n] = sum_k A[m,k]*B[n,k] ----------------
// A [M,K], B [N,K] fp16 k-contig. 128x128 CTA, 8 warps 64x32, K-chunk 64 halves.
#define HW 36
#define HTILE_WORDS (128*HW)
#define GSMEM_BYTES (2*2*HTILE_WORDS*4)   // 73728

template<bool OUT_HALF>
__global__ __launch_bounds__(256, 2)
void h16_gemm(const __half* __restrict__ A, const __half* __restrict__ B,
              void* __restrict__ Cv, const float* __restrict__ bias, int K, int ldc)
{
    extern __shared__ __align__(16) uint32_t smw[];
    const int tid = threadIdx.x, w = tid >> 5, t = tid & 31;
    const int m0 = blockIdx.x * 128, n0 = blockIdx.y * 128;
    const int wm = (w >> 2) * 64, wn = (w & 3) * 32;
    const int g = t >> 2, th = t & 3;

    float acc[4][4][4];
#pragma unroll
    for (int mt = 0; mt < 4; mt++)
#pragma unroll
        for (int nt = 0; nt < 4; nt++)
#pragma unroll
            for (int r = 0; r < 4; r++) acc[mt][nt][r] = 0.0f;

    const int lr = tid >> 3;           // 0..31
    const int lh = (tid & 7) * 8;      // half offset within 64
    const int lw = (tid & 7) * 4;      // word offset within 32

#define PREFETCH(kt, s) do {                                                   \
        uint32_t* As_ = smw + (s) * 2 * HTILE_WORDS;                           \
        uint32_t* Bs_ = As_ + HTILE_WORDS;                                     \
        const __half* Ag_ = A + (size_t)(m0) * K + (kt) * 64;                  \
        const __half* Bg_ = B + (size_t)(n0) * K + (kt) * 64;                  \
        _Pragma("unroll")                                                      \
        for (int p_ = 0; p_ < 4; p_++) {                                       \
            int r_ = p_ * 32 + lr;                                             \
            cpa16(smem_u32(&As_[r_ * HW + lw]), Ag_ + (size_t)r_ * K + lh);    \
            cpa16(smem_u32(&Bs_[r_ * HW + lw]), Bg_ + (size_t)r_ * K + lh);    \
        }                                                                      \
    } while (0)

    const int NT = K >> 6;
    PREFETCH(0, 0);
    CP_COMMIT();

    for (int kt = 0; kt < NT; kt++) {
        const int s = kt & 1;
        if (kt + 1 < NT) { PREFETCH(kt + 1, s ^ 1); CP_COMMIT(); CP_WAIT(1); }
        else             { CP_WAIT(0); }
        __syncthreads();

        const uint32_t* Asu = smw + s * 2 * HTILE_WORDS;
        const uint32_t* Bsu = Asu + HTILE_WORDS;
#pragma unroll
        for (int ks = 0; ks < 4; ks++) {
            const int kw = ks * 8;
            uint32_t af[4][4], bf[4][2];
#pragma unroll
            for (int mt = 0; mt < 4; mt++) {
                int rb = wm + mt * 16 + g;
                af[mt][0] = Asu[rb * HW + kw + th];
                af[mt][1] = Asu[(rb + 8) * HW + kw + th];
                af[mt][2] = Asu[rb * HW + kw + th + 4];
                af[mt][3] = Asu[(rb + 8) * HW + kw + th + 4];
            }
#pragma unroll
            for (int nt = 0; nt < 4; nt++) {
                int rb = wn + nt * 8 + g;
                bf[nt][0] = Bsu[rb * HW + kw + th];
                bf[nt][1] = Bsu[rb * HW + kw + th + 4];
            }
#pragma unroll
            for (int mt = 0; mt < 4; mt++)
#pragma unroll
                for (int nt = 0; nt < 4; nt++)
                    MMA_F16(acc[mt][nt], af[mt][0], af[mt][1], af[mt][2], af[mt][3],
                            bf[nt][0], bf[nt][1]);
        }
        __syncthreads();
    }
#undef PREFETCH

#pragma unroll
    for (int mt = 0; mt < 4; mt++) {
        const int row = m0 + wm + mt * 16 + g;
#pragma unroll
        for (int nt = 0; nt < 4; nt++) {
            const int col = n0 + wn + nt * 8 + 2 * th;
            if (OUT_HALF) {
                __half* C = (__half*)Cv;
                *(uint32_t*)&C[(size_t)row * ldc + col]       = pkh2(acc[mt][nt][0], acc[mt][nt][1]);
                *(uint32_t*)&C[(size_t)(row + 8) * ldc + col] = pkh2(acc[mt][nt][2], acc[mt][nt][3]);
            } else {
                float* C = (float*)Cv;
                float2 v0 = make_float2(acc[mt][nt][0], acc[mt][nt][1]);
                float2 v1 = make_float2(acc[mt][nt][2], acc[mt][nt][3]);
                if (bias) {
                    float b0 = bias[col], b1 = bias[col + 1];
                    v0.x += b0; v0.y += b1; v1.x += b0; v1.y += b1;
                }
                *(float2*)&C[(size_t)row * ldc + col]       = v0;
                *(float2*)&C[(size_t)(row + 8) * ldc + col] = v1;
            }
        }
    }
}

// ---------------- flash3: fp16 tensor-core flash attention with rel skew ----------------
// CTA = 128 q-rows x 64-kv tiles, 8 warps x 16 rows. All tiles fp16, fp32 accum.
// rel[n,m] = q_n . Er[1023-(n-m)]; 80-wide banded R-GEMM per warp, smem gather.
#define FLK 0
#define FLV (64*36)
#define FLE (FLV + 64*36)
#define FLR (FLE + 192*36)
#define FL_WORDS (FLR + 8*16*84)
#define FL_SMEM_BYTES (FL_WORDS*4)   // 89088

__global__ __launch_bounds__(256, 2)
void flash3_kernel(const __half* __restrict__ qkv, const __half* __restrict__ Erh,
                   __half* __restrict__ attn)
{
    extern __shared__ __align__(16) uint32_t smw[];
    uint32_t* Ksm = smw + FLK;          // K[kv][hd] 64x(32w+4)
    uint32_t* Vtm = smw + FLV;          // Vt[d][kv] 64x(32w+4)
    uint32_t* Esm = smw + FLE;          // E'[j][hd] 192x(32w+4)
    float*    Rst = (float*)(smw + FLR);// 8 x 16 x 84 (also Q staging)

    const int tid = threadIdx.x;
    const int w = tid >> 5, lane = tid & 31;
    const int qr = lane >> 2, qc = lane & 3;
    const int z = blockIdx.x;
    const int b = z >> 4, h = z & 15;
    const int i0 = (7 - (int)blockIdx.y) * 128;   // heavy q-tiles first
    const int ntiles = (i0 >> 6) + 2;

    const __half* qg = qkv + (size_t)b * SEQ * (3*DIMC) + h * HD;
    const __half* kg = qg + DIMC;
    const __half* vg = qg + 2*DIMC;

    float* Rwf = Rst + w * (16*84);

    // ---- stage Q tile (fp16 copy), load persistent A-frags ----
    {
        uint32_t* Qs = (uint32_t*)Rst;
#pragma unroll
        for (int s = 0; s < 4; s++) {
            int idx = tid + (s << 8);
            int row = idx >> 3, w4 = (idx & 7) * 4;
            uint4 t = *(const uint4*)(qg + (size_t)(i0 + row) * (3*DIMC) + w4*2);
            *(uint4*)&Qs[row * 36 + w4] = t;
        }
    }
    __syncthreads();
    uint32_t qa[4][4];
    {
        const uint32_t* Qs = (const uint32_t*)Rst;
        const int ro = (16*w + qr) * 36 + qc;
        const int r8 = ro + 8*36;
#pragma unroll
        for (int ks = 0; ks < 4; ks++) {
            qa[ks][0] = Qs[ro + 8*ks];
            qa[ks][1] = Qs[r8 + 8*ks];
            qa[ks][2] = Qs[ro + 8*ks + 4];
            qa[ks][3] = Qs[r8 + 8*ks + 4];
        }
    }
    __syncthreads();

    float oa[8][4];
#pragma unroll
    for (int nf = 0; nf < 8; nf++) { oa[nf][0]=0.f; oa[nf][1]=0.f; oa[nf][2]=0.f; oa[nf][3]=0.f; }
    float mA = -1e30f, mB = -1e30f, lA = 0.f, lB = 0.f;
    const int rowA = i0 + 16*w + qr;
    const int rowB = rowA + 8;
    const float SC = 0.18033688011112042f;   // 0.125 * log2(e)

    for (int kt = 0; kt < ntiles; kt++) {
        const int kt0 = kt << 6;
        __syncthreads();

        // K tile: direct fp16 copy
#pragma unroll
        for (int s = 0; s < 2; s++) {
            int idx = tid + (s << 8);
            int row = idx >> 3, w4 = (idx & 7) * 4;
            uint4 t = *(const uint4*)(kg + (size_t)(kt0 + row) * (3*DIMC) + w4*2);
            *(uint4*)&Ksm[row * 36 + w4] = t;
        }
        // V tile transposed: Vt[d][kv]
        {
            __half* Vth = (__half*)Vtm;
#pragma unroll
            for (int s = 0; s < 2; s++) {
                int idx = tid + (s << 8);
                int row = idx >> 3, d0 = (idx & 7) * 8;
                uint4 t = *(const uint4*)(vg + (size_t)(kt0 + row) * (3*DIMC) + d0);
                const __half* hp = (const __half*)&t;
#pragma unroll
                for (int j = 0; j < 8; j++) Vth[(d0 + j) * 72 + row] = hp[j];
            }
        }
        // Er window: row jw -> Er[1087 - i0 + kt0 - jw] (clamped; invalid masked later)
        const int ebase = 1087 - i0 + kt0;
#pragma unroll
        for (int s = 0; s < 6; s++) {
            int idx = tid + (s << 8);
            int row = idx >> 3, w4 = (idx & 7) * 4;
            int ei = ebase - row;
            ei = ei < 0 ? 0 : (ei > 1023 ? 1023 : ei);
            uint4 t = *(const uint4*)(Erh + (size_t)ei * HD + w4*2);
            *(uint4*)&Esm[row * 36 + w4] = t;
        }
        __syncthreads();

        // ---- S = Q K^T ----
        float sacc[8][4];
#pragma unroll
        for (int nf = 0; nf < 8; nf++) { sacc[nf][0]=0.f; sacc[nf][1]=0.f; sacc[nf][2]=0.f; sacc[nf][3]=0.f; }
#pragma unroll
        for (int ks = 0; ks < 4; ks++)
#pragma unroll
            for (int nf = 0; nf < 8; nf++) {
                uint32_t b0 = Ksm[(8*nf + qr)*36 + 8*ks + qc];
                uint32_t b1 = Ksm[(8*nf + qr)*36 + 8*ks + qc + 4];
                MMA_F16(sacc[nf], qa[ks][0], qa[ks][1], qa[ks][2], qa[ks][3], b0, b1);
            }

        // ---- R = Q E'^T (80-wide band), two 5-block halves to cap registers ----
#pragma unroll
        for (int hv = 0; hv < 2; hv++) {
            float racc[5][4];
#pragma unroll
            for (int j = 0; j < 5; j++) { racc[j][0]=0.f; racc[j][1]=0.f; racc[j][2]=0.f; racc[j][3]=0.f; }
#pragma unroll
            for (int ks = 0; ks < 4; ks++)
#pragma unroll
                for (int j = 0; j < 5; j++) {
                    int jj = hv*5 + j;
                    uint32_t b0 = Esm[(16*w + 8*jj + qr)*36 + 8*ks + qc];
                    uint32_t b1 = Esm[(16*w + 8*jj + qr)*36 + 8*ks + qc + 4];
                    MMA_F16(racc[j], qa[ks][0], qa[ks][1], qa[ks][2], qa[ks][3], b0, b1);
                }
#pragma unroll
            for (int j = 0; j < 5; j++) {
                int cb = 8*(hv*5 + j) + 2*qc;
                Rwf[qr*84 + cb]         = racc[j][0];
                Rwf[qr*84 + cb + 1]     = racc[j][1];
                Rwf[(qr+8)*84 + cb]     = racc[j][2];
                Rwf[(qr+8)*84 + cb + 1] = racc[j][3];
            }
        }
        __syncwarp();

        // ---- combine + mask (log2-scaled) ----
#pragma unroll
        for (int nf = 0; nf < 8; nf++) {
            int c0 = 8*nf + 2*qc;
            int jA = qr - c0 + 64;
            float rA0 = Rwf[qr*84 + jA];
            float rA1 = Rwf[qr*84 + jA - 1];
            float rB0 = Rwf[(qr+8)*84 + jA + 8];
            float rB1 = Rwf[(qr+8)*84 + jA + 7];
            int mg = kt0 + c0;
            sacc[nf][0] = (mg     <= rowA) ? (sacc[nf][0] + rA0) * SC : -1e30f;
            sacc[nf][1] = (mg + 1 <= rowA) ? (sacc[nf][1] + rA1) * SC : -1e30f;
            sacc[nf][2] = (mg     <= rowB) ? (sacc[nf][2] + rB0) * SC : -1e30f;
            sacc[nf][3] = (mg + 1 <= rowB) ? (sacc[nf][3] + rB1) * SC : -1e30f;
        }

        // ---- online softmax (quad shfl) ----
        float tmA = -1e30f, tmB = -1e30f;
#pragma unroll
        for (int nf = 0; nf < 8; nf++) {
            tmA = fmaxf(tmA, fmaxf(sacc[nf][0], sacc[nf][1]));
            tmB = fmaxf(tmB, fmaxf(sacc[nf][2], sacc[nf][3]));
        }
        tmA = fmaxf(tmA, __shfl_xor_sync(0xffffffffu, tmA, 1));
        tmA = fmaxf(tmA, __shfl_xor_sync(0xffffffffu, tmA, 2));
        tmB = fmaxf(tmB, __shfl_xor_sync(0xffffffffu, tmB, 1));
        tmB = fmaxf(tmB, __shfl_xor_sync(0xffffffffu, tmB, 2));
        float nmA = fmaxf(mA, tmA), nmB = fmaxf(mB, tmB);
        float aAs = exp2f(mA - nmA), aBs = exp2f(mB - nmB);
        mA = nmA; mB = nmB;

        float sA = 0.f, sB = 0.f;
#pragma unroll
        for (int nf = 0; nf < 8; nf++) {
            sacc[nf][0] = exp2f(sacc[nf][0] - mA);
            sacc[nf][1] = exp2f(sacc[nf][1] - mA);
            sacc[nf][2] = exp2f(sacc[nf][2] - mB);
            sacc[nf][3] = exp2f(sacc[nf][3] - mB);
            sA += sacc[nf][0] + sacc[nf][1];
            sB += sacc[nf][2] + sacc[nf][3];
            oa[nf][0] *= aAs; oa[nf][1] *= aAs;
            oa[nf][2] *= aBs; oa[nf][3] *= aBs;
        }
        sA += __shfl_xor_sync(0xffffffffu, sA, 1);
        sA += __shfl_xor_sync(0xffffffffu, sA, 2);
        sB += __shfl_xor_sync(0xffffffffu, sB, 1);
        sB += __shfl_xor_sync(0xffffffffu, sB, 2);
        lA = lA * aAs + sA;
        lB = lB * aBs + sB;

        // ---- O += P V : P repacked to fp16 A-frags in registers (no smem) ----
#pragma unroll
        for (int ks = 0; ks < 4; ks++) {
            uint32_t p0 = pkh2(sacc[2*ks][0],   sacc[2*ks][1]);
            uint32_t p1 = pkh2(sacc[2*ks][2],   sacc[2*ks][3]);
            uint32_t p2 = pkh2(sacc[2*ks+1][0], sacc[2*ks+1][1]);
            uint32_t p3 = pkh2(sacc[2*ks+1][2], sacc[2*ks+1][3]);
#pragma unroll
            for (int nf = 0; nf < 8; nf++) {
                uint32_t b0 = Vtm[(8*nf + qr)*36 + 8*ks + qc];
                uint32_t b1 = Vtm[(8*nf + qr)*36 + 8*ks + qc + 4];
                MMA_F16(oa[nf], p0, p1, p2, p3, b0, b1);
            }
        }
    }

    // ---- epilogue: normalize, write fp16 attn ----
    const float invA = 1.f / lA, invB = 1.f / lB;
#pragma unroll
    for (int nf = 0; nf < 8; nf++) {
        int d = h*HD + 8*nf + 2*qc;
        *(uint32_t*)&attn[((size_t)b*SEQ + rowA)*DIMC + d] = pkh2(oa[nf][0]*invA, oa[nf][1]*invA);
        *(uint32_t*)&attn[((size_t)b*SEQ + rowB)*DIMC + d] = pkh2(oa[nf][2]*invB, oa[nf][3]*invB);
    }
}

// ---------------- launch ----------------
extern "C" void kernel_launch(void* const* d_in, const int* in_sizes, int n_in,
                              void* d_out, int out_size)
{
    const float* x     = (const float*)d_in[0];
    const float* Wqkv  = (const float*)d_in[1];
    const float* Wproj = (const float*)d_in[2];
    const float* bproj = (const float*)d_in[3];
    const float* Er    = (const float*)d_in[4];
    float* out = (float*)d_out;

    __half *qkvh, *xh, *wqkvh, *wprojh, *erh, *attnh;
    cudaGetSymbolAddress((void**)&qkvh,  g_qkvh);
    cudaGetSymbolAddress((void**)&xh,    g_xh);
    cudaGetSymbolAddress((void**)&wqkvh, g_wqkvh);
    cudaGetSymbolAddress((void**)&wprojh,g_wprojh);
    cudaGetSymbolAddress((void**)&erh,   g_erh);
    cudaGetSymbolAddress((void**)&attnh, g_attnh);

    cudaFuncSetAttribute(h16_gemm<true>,  cudaFuncAttributeMaxDynamicSharedMemorySize, GSMEM_BYTES);
    cudaFuncSetAttribute(h16_gemm<false>, cudaFuncAttributeMaxDynamicSharedMemorySize, GSMEM_BYTES);
    cudaFuncSetAttribute(flash3_kernel,   cudaFuncAttributeMaxDynamicSharedMemorySize, FL_SMEM_BYTES);

    // 1) fp16 conversions
    conv_h16<<<BATCH*SEQ*DIMC/8/256, 256>>>(x,     xh,     BATCH*SEQ*DIMC);
    conv_h16<<<3*DIMC*DIMC/8/256,   256>>>(Wqkv,  wqkvh,  3*DIMC*DIMC);
    conv_h16<<<DIMC*DIMC/8/256,     256>>>(Wproj, wprojh, DIMC*DIMC);
    conv_h16<<<SEQ*HD/8/256,        256>>>(Er,    erh,    SEQ*HD);

    // 2) qkv = x @ Wqkv^T  (M=4096, N=3072, K=1024), fp16 out
    h16_gemm<true><<<dim3(32, 24), 256, GSMEM_BYTES>>>(xh, wqkvh, qkvh, nullptr, DIMC, 3*DIMC);

    // 3) fp16 tensor-core flash attention (fp16 attn out)
    flash3_kernel<<<dim3(64, 8), 256, FL_SMEM_BYTES>>>(qkvh, erh, attnh);

    // 4) out = attn @ Wproj^T + b  (M=4096, N=1024, K=1024), fp32 out
    h16_gemm<false><<<dim3(32, 8), 256, GSMEM_BYTES>>>(attnh, wprojh, out, bproj, DIMC, DIMC);
}